// round 1
// baseline (speedup 1.0000x reference)
#include <cuda_runtime.h>
#include <math.h>

// Problem constants
#define HH 256      // rows (seq for width attention)
#define WW 256      // cols (seq for height attention)
#define DD 64       // model dim
#define NH 8        // heads
#define DHD 64      // dim per head
#define INNER 512   // NH*DHD
#define KBIG 16384  // HH*DHD (height dots contraction length)

// ---------------- scratch (device globals: allocation-free rule) -------------
__device__ float g_QH[NH * WW * HH * DHD];  // [head][i(w)][r*64+c]  (128 MiB)
__device__ float g_KH[NH * WW * HH * DHD];  // [head][j(w)][r*64+c]  (128 MiB)
__device__ float g_VH[HH * WW * INNER];     // [r][j][head*64+c]     (128 MiB)
__device__ float g_DOTS[NH * WW * WW];      // [head][i][j]          (2 MiB)
__device__ float g_PB[NH * WW * WW];        // [head][i][j]          (2 MiB)

// ---------------- init: bias into output, zero dots scratch ------------------
__global__ void k_init(const float* __restrict__ bw, const float* __restrict__ bh,
                       float* __restrict__ out) {
    int idx = blockIdx.x * 256 + threadIdx.x;
    out[idx] = 0.5f * (bw[idx & 63] + bh[idx & 63]);
}

__global__ void k_zero_dots() {
    int idx = blockIdx.x * 256 + threadIdx.x;
    g_DOTS[idx] = 0.f;
}

// ---------------- helpers -----------------------------------------------------
__device__ __forceinline__ void proj_row(const float* __restrict__ xs,
                                         const float* __restrict__ wt,
                                         int t, float* a) {
    // a[c] = sum_d xs[d][t] * wt[d][c], c = 0..63
#pragma unroll
    for (int c = 0; c < 64; c++) a[c] = 0.f;
    for (int d = 0; d < 64; d++) {
        float xv = xs[d * 257 + t];
        const float4* wr = (const float4*)(wt + d * 68);
#pragma unroll
        for (int c4 = 0; c4 < 16; c4++) {
            float4 wv = wr[c4];
            a[c4 * 4 + 0] = fmaf(xv, wv.x, a[c4 * 4 + 0]);
            a[c4 * 4 + 1] = fmaf(xv, wv.y, a[c4 * 4 + 1]);
            a[c4 * 4 + 2] = fmaf(xv, wv.z, a[c4 * 4 + 2]);
            a[c4 * 4 + 3] = fmaf(xv, wv.w, a[c4 * 4 + 3]);
        }
    }
}

// =============================================================================
// Width attention, fully fused: one block per (column w, head).
// smem: xs_t[64][257], ks[256][68], vs[256][68], wt[64][68]  (~217 KB)
// =============================================================================
__global__ void __launch_bounds__(256, 1)
k_width(const float* __restrict__ x, const float* __restrict__ Wq,
        const float* __restrict__ Wkv, const float* __restrict__ Wout,
        float* __restrict__ out) {
    extern __shared__ float sm[];
    float* xs = sm;                  // 64*257
    float* ks = xs + 64 * 257;       // 256*68
    float* vs = ks + 256 * 68;       // 256*68
    float* wt = vs + 256 * 68;       // 64*68

    const int t = threadIdx.x;
    const int w = blockIdx.x;
    const int head = blockIdx.y;

    // load x column w, transposed: xs[d][i]
    for (int e = t; e < HH * DD; e += 256) {
        int i = e >> 6, d = e & 63;
        xs[d * 257 + i] = x[(size_t)i * (WW * DD) + w * DD + d];
    }
    // load K weight slice
    for (int e = t; e < 4096; e += 256) {
        int d = e >> 6, c = e & 63;
        wt[d * 68 + c] = Wkv[d * 1024 + head * 64 + c];
    }
    __syncthreads();

    float a[64];
    // K rows into smem
    proj_row(xs, wt, t, a);
    {
        float4* kr = (float4*)(ks + t * 68);
#pragma unroll
        for (int c4 = 0; c4 < 16; c4++)
            kr[c4] = make_float4(a[c4 * 4], a[c4 * 4 + 1], a[c4 * 4 + 2], a[c4 * 4 + 3]);
    }
    __syncthreads();
    // V weight slice
    for (int e = t; e < 4096; e += 256) {
        int d = e >> 6, c = e & 63;
        wt[d * 68 + c] = Wkv[d * 1024 + 512 + head * 64 + c];
    }
    __syncthreads();
    proj_row(xs, wt, t, a);
    {
        float4* vr = (float4*)(vs + t * 68);
#pragma unroll
        for (int c4 = 0; c4 < 16; c4++)
            vr[c4] = make_float4(a[c4 * 4], a[c4 * 4 + 1], a[c4 * 4 + 2], a[c4 * 4 + 3]);
    }
    __syncthreads();
    // Q weight slice
    for (int e = t; e < 4096; e += 256) {
        int d = e >> 6, c = e & 63;
        wt[d * 68 + c] = Wq[d * 512 + head * 64 + c];
    }
    __syncthreads();
    float q[64];
    proj_row(xs, wt, t, q);
    __syncthreads();
    // stage out-projection weight slice (read only after the post-loop sync)
    for (int e = t; e < 4096; e += 256) {
        int c = e >> 6, d = e & 63;
        wt[c * 68 + d] = Wout[(head * 64 + c) * 64 + d];
    }

    // ---- online-softmax attention over 256 keys, row = t ----
    float m = -1e30f, l = 0.f;
    float acc[64];
#pragma unroll
    for (int c = 0; c < 64; c++) acc[c] = 0.f;

    for (int jt = 0; jt < 32; jt++) {
        float s[8];
        float mt = m;
#pragma unroll
        for (int jj = 0; jj < 8; jj++) {
            const float4* kr = (const float4*)(ks + (jt * 8 + jj) * 68);
            float dsum = 0.f;
#pragma unroll
            for (int c4 = 0; c4 < 16; c4++) {
                float4 kv = kr[c4];
                dsum = fmaf(q[c4 * 4 + 0], kv.x, dsum);
                dsum = fmaf(q[c4 * 4 + 1], kv.y, dsum);
                dsum = fmaf(q[c4 * 4 + 2], kv.z, dsum);
                dsum = fmaf(q[c4 * 4 + 3], kv.w, dsum);
            }
            s[jj] = dsum * 0.125f;
            mt = fmaxf(mt, s[jj]);
        }
        float corr = __expf(m - mt);
        m = mt;
        l *= corr;
#pragma unroll
        for (int c = 0; c < 64; c++) acc[c] *= corr;
#pragma unroll
        for (int jj = 0; jj < 8; jj++) {
            float p = __expf(s[jj] - m);
            l += p;
            const float4* vr = (const float4*)(vs + (jt * 8 + jj) * 68);
#pragma unroll
            for (int c4 = 0; c4 < 16; c4++) {
                float4 vv = vr[c4];
                acc[c4 * 4 + 0] = fmaf(p, vv.x, acc[c4 * 4 + 0]);
                acc[c4 * 4 + 1] = fmaf(p, vv.y, acc[c4 * 4 + 1]);
                acc[c4 * 4 + 2] = fmaf(p, vv.z, acc[c4 * 4 + 2]);
                acc[c4 * 4 + 3] = fmaf(p, vv.w, acc[c4 * 4 + 3]);
            }
        }
    }
    __syncthreads();  // wt now holds Wout slice, visible

    // ---- fused out-projection: contribution[d] = sum_c (acc[c]/l) * Wout[c][d]
    float inv = 1.f / l;
    float oc[64];
#pragma unroll
    for (int d = 0; d < 64; d++) oc[d] = 0.f;
#pragma unroll
    for (int c = 0; c < 64; c++) {
        float ov = acc[c] * inv;
        const float4* wr = (const float4*)(wt + c * 68);
#pragma unroll
        for (int d4 = 0; d4 < 16; d4++) {
            float4 wv = wr[d4];
            oc[d4 * 4 + 0] = fmaf(ov, wv.x, oc[d4 * 4 + 0]);
            oc[d4 * 4 + 1] = fmaf(ov, wv.y, oc[d4 * 4 + 1]);
            oc[d4 * 4 + 2] = fmaf(ov, wv.z, oc[d4 * 4 + 2]);
            oc[d4 * 4 + 3] = fmaf(ov, wv.w, oc[d4 * 4 + 3]);
        }
    }
    // w_out[h=t, w, d]
    float* op = out + ((size_t)t * WW + w) * DD;
#pragma unroll
    for (int d = 0; d < 64; d++) atomicAdd(op + d, 0.5f * oc[d]);
}

// =============================================================================
// Height QKV projection: one block per row r; thread t = token (col) i.
// Writes QH/KH in [head][pos][r*64+c] layout (contiguous K for the big GEMM)
// and VH in [r][j][head*64+c].
// =============================================================================
__global__ void __launch_bounds__(256, 1)
k_hproj(const float* __restrict__ x, const float* __restrict__ Wq,
        const float* __restrict__ Wkv) {
    extern __shared__ float sm[];
    float* xs = sm;              // 64*257
    float* wt = xs + 64 * 257;   // 64*68

    const int t = threadIdx.x;
    const int r = blockIdx.x;

    for (int e = t; e < HH * DD; e += 256) {
        int i = e >> 6, d = e & 63;
        xs[d * 257 + i] = x[(size_t)r * (WW * DD) + e];
        (void)i; (void)d;
    }
    // rewrite with transpose index (above stored linearly by e; fix layout):
    __syncthreads();

    float a[64];
    for (int mkind = 0; mkind < 3; mkind++) {
        for (int g = 0; g < 8; g++) {
            __syncthreads();
            for (int e = t; e < 4096; e += 256) {
                int d = e >> 6, c = e & 63;
                float wv;
                if (mkind == 0)      wv = Wq[d * 512 + g * 64 + c];
                else if (mkind == 1) wv = Wkv[d * 1024 + g * 64 + c];
                else                 wv = Wkv[d * 1024 + 512 + g * 64 + c];
                wt[d * 68 + c] = wv;
            }
            __syncthreads();
            proj_row(xs, wt, t, a);
            float* dst;
            if (mkind == 0)      dst = g_QH + ((size_t)(g * 256 + t)) * KBIG + r * 64;
            else if (mkind == 1) dst = g_KH + ((size_t)(g * 256 + t)) * KBIG + r * 64;
            else                 dst = g_VH + ((size_t)(r * 256 + t)) * INNER + g * 64;
            float4* d4 = (float4*)dst;
#pragma unroll
            for (int c4 = 0; c4 < 16; c4++)
                d4[c4] = make_float4(a[c4 * 4], a[c4 * 4 + 1], a[c4 * 4 + 2], a[c4 * 4 + 3]);
        }
    }
}

// =============================================================================
// Pair bias: layernorm(pair_bias[i,j,:]) @ W_pair -> g_PB[head][i][j]
// One warp per (i,j) pair; 8 warps per block.
// =============================================================================
__global__ void k_pair(const float* __restrict__ pb, const float* __restrict__ g,
                       const float* __restrict__ b, const float* __restrict__ Wp) {
    __shared__ float swp[128 * 8];
    __shared__ float sg[128], sb[128];
    const int t = threadIdx.x;
    if (t < 128) { sg[t] = g[t]; sb[t] = b[t]; }
    for (int e = t; e < 1024; e += 256) swp[e] = Wp[e];
    __syncthreads();

    const int warp = t >> 5, lane = t & 31;
    const int gw = blockIdx.x * 8 + warp;  // pair index (i*256+j)
    const int i = gw >> 8, j = gw & 255;

    const float4* src = (const float4*)(pb + (size_t)gw * 128);
    float4 v = src[lane];
    float s1 = v.x + v.y + v.z + v.w;
    float s2 = v.x * v.x + v.y * v.y + v.z * v.z + v.w * v.w;
#pragma unroll
    for (int o = 16; o; o >>= 1) {
        s1 += __shfl_xor_sync(0xffffffffu, s1, o);
        s2 += __shfl_xor_sync(0xffffffffu, s2, o);
    }
    float mu = s1 * (1.f / 128.f);
    float var = s2 * (1.f / 128.f) - mu * mu;
    float rstd = rsqrtf(var + 1e-5f);

    float ph[8];
#pragma unroll
    for (int h = 0; h < 8; h++) ph[h] = 0.f;
    float vv[4] = {v.x, v.y, v.z, v.w};
#pragma unroll
    for (int qi = 0; qi < 4; qi++) {
        int p = lane * 4 + qi;
        float n = (vv[qi] - mu) * rstd * sg[p] + sb[p];
#pragma unroll
        for (int h = 0; h < 8; h++) ph[h] = fmaf(n, swp[p * 8 + h], ph[h]);
    }
#pragma unroll
    for (int h = 0; h < 8; h++) {
#pragma unroll
        for (int o = 16; o; o >>= 1) ph[h] += __shfl_xor_sync(0xffffffffu, ph[h], o);
    }
    if (lane == 0) {
#pragma unroll
        for (int h = 0; h < 8; h++) g_PB[h * 65536 + i * 256 + j] = ph[h];
    }
}

// =============================================================================
// Height dots: per head, DOTS[i][j] += QH[i][k-chunk] . KH[j][k-chunk]
// grid (kchunk=8, itile=4, head=8), 8x8 register tile per thread.
// =============================================================================
__global__ void __launch_bounds__(256, 1) k_hdots() {
    extern __shared__ float sm[];
    float* Qs = sm;            // 64*68
    float* Ks = Qs + 64 * 68;  // 256*68

    const int t = threadIdx.x;
    const int kc = blockIdx.x;    // 0..7
    const int it = blockIdx.y;    // 0..3
    const int head = blockIdx.z;  // 0..7
    const int i0 = it * 64;
    const int tx = t & 31, ty = t >> 5;

    float acc[64];
#pragma unroll
    for (int c = 0; c < 64; c++) acc[c] = 0.f;

    for (int stp = 0; stp < 32; stp++) {
        const int k0 = kc * 2048 + stp * 64;
        __syncthreads();
        for (int e = t; e < 4096; e += 256) {
            int ii = e >> 6, kk = e & 63;
            Qs[ii * 68 + kk] = g_QH[(size_t)(head * 256 + i0 + ii) * KBIG + k0 + kk];
        }
        for (int e = t; e < 16384; e += 256) {
            int j = e >> 6, kk = e & 63;
            Ks[j * 68 + kk] = g_KH[(size_t)(head * 256 + j) * KBIG + k0 + kk];
        }
        __syncthreads();

        for (int kk = 0; kk < 64; kk += 4) {
            float4 aq[8], bk[8];
#pragma unroll
            for (int ii = 0; ii < 8; ii++)
                aq[ii] = *(const float4*)(Qs + (ty * 8 + ii) * 68 + kk);
#pragma unroll
            for (int jj = 0; jj < 8; jj++)
                bk[jj] = *(const float4*)(Ks + (tx + jj * 32) * 68 + kk);
#pragma unroll
            for (int ii = 0; ii < 8; ii++) {
#pragma unroll
                for (int jj = 0; jj < 8; jj++) {
                    float s = acc[ii * 8 + jj];
                    s = fmaf(aq[ii].x, bk[jj].x, s);
                    s = fmaf(aq[ii].y, bk[jj].y, s);
                    s = fmaf(aq[ii].z, bk[jj].z, s);
                    s = fmaf(aq[ii].w, bk[jj].w, s);
                    acc[ii * 8 + jj] = s;
                }
            }
        }
    }
#pragma unroll
    for (int ii = 0; ii < 8; ii++) {
#pragma unroll
        for (int jj = 0; jj < 8; jj++) {
            atomicAdd(&g_DOTS[head * 65536 + (i0 + ty * 8 + ii) * 256 + tx + jj * 32],
                      acc[ii * 8 + jj]);
        }
    }
}

// =============================================================================
// Height softmax: row = (head, i); scale dots, add pair bias, softmax in place.
// =============================================================================
__global__ void k_hsm() {
    const int t = threadIdx.x, warp = t >> 5, lane = t & 31;
    const int row = blockIdx.x * 8 + warp;  // head*256 + i

    float v[8];
    float mx = -1e30f;
#pragma unroll
    for (int kk = 0; kk < 8; kk++) {
        int j = kk * 32 + lane;
        v[kk] = g_DOTS[row * 256 + j] * 0.0078125f + g_PB[row * 256 + j];
        mx = fmaxf(mx, v[kk]);
    }
#pragma unroll
    for (int o = 16; o; o >>= 1) mx = fmaxf(mx, __shfl_xor_sync(0xffffffffu, mx, o));
    float s = 0.f;
#pragma unroll
    for (int kk = 0; kk < 8; kk++) {
        v[kk] = __expf(v[kk] - mx);
        s += v[kk];
    }
#pragma unroll
    for (int o = 16; o; o >>= 1) s += __shfl_xor_sync(0xffffffffu, s, o);
    float inv = 1.f / s;
#pragma unroll
    for (int kk = 0; kk < 8; kk++) g_DOTS[row * 256 + kk * 32 + lane] = v[kk] * inv;
}

// =============================================================================
// Height AV + out-projection: one block per (row r, head); thread t = col i.
// =============================================================================
__global__ void __launch_bounds__(256, 1)
k_hav(const float* __restrict__ Wout, float* __restrict__ out) {
    extern __shared__ float sm[];
    float* vs = sm;               // 256*68
    float* ats = vs + 256 * 68;   // 256*68
    float* wt = ats + 256 * 68;   // 64*68

    const int t = threadIdx.x;
    const int r = blockIdx.x;
    const int head = blockIdx.y;

    for (int e = t; e < 16384; e += 256) {
        int j = e >> 6, c = e & 63;
        vs[j * 68 + c] = g_VH[(size_t)(r * 256 + j) * INNER + head * 64 + c];
    }
    for (int e = t; e < 4096; e += 256) {
        int c = e >> 6, d = e & 63;
        wt[c * 68 + d] = Wout[(head * 64 + c) * 64 + d];
    }

    float acc[64];
#pragma unroll
    for (int c = 0; c < 64; c++) acc[c] = 0.f;

    for (int jt = 0; jt < 4; jt++) {
        __syncthreads();
        for (int e = t; e < 16384; e += 256) {
            int ii = e >> 6, jj = e & 63;
            ats[ii * 68 + jj] = g_DOTS[head * 65536 + ii * 256 + jt * 64 + jj];
        }
        __syncthreads();
        for (int jj4 = 0; jj4 < 16; jj4++) {
            float4 p4 = *(const float4*)(ats + t * 68 + jj4 * 4);
            float pv[4] = {p4.x, p4.y, p4.z, p4.w};
#pragma unroll
            for (int u = 0; u < 4; u++) {
                float p = pv[u];
                const float4* vr = (const float4*)(vs + (size_t)(jt * 64 + jj4 * 4 + u) * 68);
#pragma unroll
                for (int c4 = 0; c4 < 16; c4++) {
                    float4 vv = vr[c4];
                    acc[c4 * 4 + 0] = fmaf(p, vv.x, acc[c4 * 4 + 0]);
                    acc[c4 * 4 + 1] = fmaf(p, vv.y, acc[c4 * 4 + 1]);
                    acc[c4 * 4 + 2] = fmaf(p, vv.z, acc[c4 * 4 + 2]);
                    acc[c4 * 4 + 3] = fmaf(p, vv.w, acc[c4 * 4 + 3]);
                }
            }
        }
    }

    float oc[64];
#pragma unroll
    for (int d = 0; d < 64; d++) oc[d] = 0.f;
#pragma unroll
    for (int c = 0; c < 64; c++) {
        float ov = acc[c];
        const float4* wr = (const float4*)(wt + c * 68);
#pragma unroll
        for (int d4 = 0; d4 < 16; d4++) {
            float4 wv = wr[d4];
            oc[d4 * 4 + 0] = fmaf(ov, wv.x, oc[d4 * 4 + 0]);
            oc[d4 * 4 + 1] = fmaf(ov, wv.y, oc[d4 * 4 + 1]);
            oc[d4 * 4 + 2] = fmaf(ov, wv.z, oc[d4 * 4 + 2]);
            oc[d4 * 4 + 3] = fmaf(ov, wv.w, oc[d4 * 4 + 3]);
        }
    }
    // h_out[r, i=t, d]
    float* op = out + ((size_t)r * WW + t) * DD;
#pragma unroll
    for (int d = 0; d < 64; d++) atomicAdd(op + d, 0.5f * oc[d]);
}

// =============================================================================
extern "C" void kernel_launch(void* const* d_in, const int* in_sizes, int n_in,
                              void* d_out, int out_size) {
    (void)in_sizes; (void)n_in; (void)out_size;
    const float* x      = (const float*)d_in[0];
    const float* pb     = (const float*)d_in[1];
    const float* Wq_w   = (const float*)d_in[2];
    const float* Wkv_w  = (const float*)d_in[3];
    const float* Wout_w = (const float*)d_in[4];
    const float* bout_w = (const float*)d_in[5];
    const float* Wq_h   = (const float*)d_in[6];
    const float* Wkv_h  = (const float*)d_in[7];
    const float* Wout_h = (const float*)d_in[8];
    const float* bout_h = (const float*)d_in[9];
    const float* lng    = (const float*)d_in[10];
    const float* lnb    = (const float*)d_in[11];
    const float* Wp     = (const float*)d_in[12];
    float* out = (float*)d_out;

    const int smw = (64 * 257 + 256 * 68 + 256 * 68 + 64 * 68) * (int)sizeof(float);
    const int smp = (64 * 257 + 64 * 68) * (int)sizeof(float);
    const int smd = (64 * 68 + 256 * 68) * (int)sizeof(float);
    const int sma = (256 * 68 * 2 + 64 * 68) * (int)sizeof(float);
    cudaFuncSetAttribute(k_width, cudaFuncAttributeMaxDynamicSharedMemorySize, smw);
    cudaFuncSetAttribute(k_hproj, cudaFuncAttributeMaxDynamicSharedMemorySize, smp);
    cudaFuncSetAttribute(k_hdots, cudaFuncAttributeMaxDynamicSharedMemorySize, smd);
    cudaFuncSetAttribute(k_hav, cudaFuncAttributeMaxDynamicSharedMemorySize, sma);

    k_init<<<16384, 256>>>(bout_w, bout_h, out);
    k_zero_dots<<<2048, 256>>>();
    k_hproj<<<256, 256, smp>>>(x, Wq_h, Wkv_h);
    k_pair<<<8192, 256>>>(pb, lng, lnb, Wp);
    k_hdots<<<dim3(8, 4, 8), 256, smd>>>();
    k_hsm<<<256, 256>>>();
    k_hav<<<dim3(256, 8), 256, sma>>>(Wout_h, out);
    k_width<<<dim3(256, 8), 256, smw>>>(x, Wq_w, Wkv_w, Wout_w, out);
}